// round 14
// baseline (speedup 1.0000x reference)
#include <cuda_runtime.h>

#define NB 4
#define NS 512
#define ND 256
#define NU 128
#define TI 8
#define NT (NS / TI)   // 64 i-tiles per batch

// scratch (allocation-free rule: __device__ globals)
__device__ float g_Q [NB * NS * NU];        // [row][u]    1 MB
__device__ float g_Vt[NB * NU * NS];        // [b][u][j]   1 MB

__device__ __forceinline__ float fast_tanh(float x) {
    float r;
    asm("tanh.approx.f32 %0, %1;" : "=f"(r) : "f"(x));
    return r;
}

// tanh via EX2 (MUFU rt 8) + FMA-pipe reciprocal: offloads the saturated
// MUFU.TANH pipe (rt ~16). tanh(|x|) = (1-t)/(1+t), t = e^{-2|x|}.
// 1/(1+t): quadratic minimax seed on d in [1,2] + 3 Newton steps (~1e-8).
__device__ __forceinline__ float exp_tanh(float x) {
    const float N2LOG2E = -2.885390081777927f;   // -2/ln(2)
    float t;
    asm("ex2.approx.f32 %0, %1;" : "=f"(t) : "f"(N2LOG2E * fabsf(x)));
    const float d = 1.0f + t;
    float r = fmaf(fmaf(0.333333333f, d, -1.5f), d, 2.166666667f);
    r = r * (2.0f - d * r);
    r = r * (2.0f - d * r);
    r = r * (2.0f - d * r);
    const float m = (1.0f - t) * r;
    return copysignf(m, x);
}

// ---------------------------------------------------------------------------
// Pass 1: Q = values @ Wq -> g_Q ;  V = values @ Wv -> g_Vt (transposed).
// 128 blocks x 256 thr. Block: 16 rows. Warp owns 2 rows; lane owns u-quad.
// W double-buffered in smem k-chunks of 32.
// ---------------------------------------------------------------------------
#define KC 32
__global__ __launch_bounds__(256) void proj_kernel(
    const float* __restrict__ values,
    const float* __restrict__ Wq,
    const float* __restrict__ Wv)
{
    __shared__ float4 sW[2][2][KC][NU / 4];  // [buf][mat][k][uq]  64 KB
    __shared__ float  vals[16][ND];          // 16 KB

    const int tid  = threadIdx.x;
    const int w    = tid >> 5;
    const int lane = tid & 31;
    const int r0   = blockIdx.x * 16;

    {
        const float4* g4 = (const float4*)(values + (size_t)r0 * ND);
        float4* s4 = (float4*)&vals[0][0];
#pragma unroll
        for (int i = 0; i < 4; i++)
            s4[tid + i * 256] = g4[tid + i * 256];
    }
    {
        const float4* wq4 = (const float4*)Wq;
        const float4* wv4 = (const float4*)Wv;
#pragma unroll
        for (int i = 0; i < 4; i++) {
            const int idx = tid + i * 256;
            sW[0][0][idx >> 5][idx & 31] = wq4[idx];
            sW[0][1][idx >> 5][idx & 31] = wv4[idx];
        }
    }
    __syncthreads();

    float4 aq0 = {0,0,0,0}, aq1 = {0,0,0,0};
    float4 av0 = {0,0,0,0}, av1 = {0,0,0,0};

    const float* vr0 = vals[2 * w + 0];
    const float* vr1 = vals[2 * w + 1];

#pragma unroll 1
    for (int c = 0; c < ND / KC; c++) {
        const int buf = c & 1;

        if (c + 1 < ND / KC) {
            const float4* wq4 = (const float4*)(Wq + (size_t)(c + 1) * KC * NU);
            const float4* wv4 = (const float4*)(Wv + (size_t)(c + 1) * KC * NU);
#pragma unroll
            for (int i = 0; i < 4; i++) {
                const int idx = tid + i * 256;
                sW[buf ^ 1][0][idx >> 5][idx & 31] = wq4[idx];
                sW[buf ^ 1][1][idx >> 5][idx & 31] = wv4[idx];
            }
        }

        const int kc = c * KC;
#pragma unroll 8
        for (int k = 0; k < KC; k++) {
            const float  x0 = vr0[kc + k];
            const float  x1 = vr1[kc + k];
            const float4 wq = sW[buf][0][k][lane];
            const float4 wv = sW[buf][1][k][lane];
            aq0.x += x0 * wq.x;  aq0.y += x0 * wq.y;  aq0.z += x0 * wq.z;  aq0.w += x0 * wq.w;
            aq1.x += x1 * wq.x;  aq1.y += x1 * wq.y;  aq1.z += x1 * wq.z;  aq1.w += x1 * wq.w;
            av0.x += x0 * wv.x;  av0.y += x0 * wv.y;  av0.z += x0 * wv.z;  av0.w += x0 * wv.w;
            av1.x += x1 * wv.x;  av1.y += x1 * wv.y;  av1.z += x1 * wv.z;  av1.w += x1 * wv.w;
        }
        __syncthreads();
    }

#pragma unroll
    for (int rr = 0; rr < 2; rr++) {
        const int row = r0 + 2 * w + rr;
        const float4 aq = rr ? aq1 : aq0;
        const float4 av = rr ? av1 : av0;
        ((float4*)(g_Q + (size_t)row * NU))[lane] = aq;

        const int b = row >> 9;
        const int s = row & (NS - 1);
        float* vt = g_Vt + ((size_t)b * NU + 4 * lane) * NS + s;
        vt[0 * NS] = av.x;
        vt[1 * NS] = av.y;
        vt[2 * NS] = av.z;
        vt[3 * NS] = av.w;
    }
}

// ---------------------------------------------------------------------------
// Pass 2 (fused): score + causal softmax + context.
// Block processes tile pair (NT-1-x, x): j-work uniform (520/block).
// grid (32, 4), 256 threads, <=1 block/SM.
// Phase A splits the 8 tanhs per u-iter: 3 on MUFU.TANH (rt~16), 5 on the
// EX2(rt 8) + FMA-Newton path -> MUFU pipe demand drops ~1.45x.
// ---------------------------------------------------------------------------
__global__ __launch_bounds__(256) void attn_kernel(
    const float* __restrict__ values,
    const float* __restrict__ Vw,
    float* __restrict__ out)
{
    __shared__ float4 at4[NS * 2];      // at[j][ti], 16 KB
    __shared__ float  qt[NU][TI];       // 4 KB
    __shared__ float  vw[NU];

    const int b   = blockIdx.y;
    const int tid = threadIdx.x;
    const int w    = tid >> 5;
    const int lane = tid & 31;

    if (tid < NU) vw[tid] = Vw[tid];

#pragma unroll 1
    for (int half = 0; half < 2; half++) {
        // big tile first, then its small partner
        const int it = half == 0 ? (NT - 1 - blockIdx.x) : blockIdx.x;
        const int i0 = it * TI;
        const int jcount = i0 + TI;

        // stage q transposed
        {
            const int ti = tid >> 7, u = tid & 127;  // 256 thr = 2 ti x 128 u
            qt[u][ti + 0] = g_Q[(b * NS + i0 + ti + 0) * NU + u];
            qt[u][ti + 2] = g_Q[(b * NS + i0 + ti + 2) * NU + u];
            qt[u][ti + 4] = g_Q[(b * NS + i0 + ti + 4) * NU + u];
            qt[u][ti + 6] = g_Q[(b * NS + i0 + ti + 6) * NU + u];
        }
        __syncthreads();

        // ---- Phase A: scores, warp-chunks of 32 j, 16-u pipelined loads
        {
            const int nJ32 = (jcount + 31) >> 5;
            const float4* qt4 = (const float4*)&qt[0][0];

            for (int jt = w; jt < nJ32; jt += 8) {
                const int j = jt * 32 + lane;        // always < NS
                const float* vp = g_Vt + (size_t)b * (NU * NS) + j;

                float a0 = 0.f, a1 = 0.f, a2 = 0.f, a3 = 0.f;
                float a4 = 0.f, a5 = 0.f, a6 = 0.f, a7 = 0.f;

                float vb[16];
#pragma unroll
                for (int i = 0; i < 16; i++)         // prime: 16 LDGs in flight
                    vb[i] = vp[i * NS];

#pragma unroll 1
                for (int ub = 0; ub < NU - 16; ub += 16) {
                    float vn[16];
#pragma unroll
                    for (int i = 0; i < 16; i++)     // prefetch next chunk
                        vn[i] = vp[(ub + 16 + i) * NS];
#pragma unroll
                    for (int i = 0; i < 16; i++) {
                        const int u = ub + i;
                        const float v  = vb[i];
                        const float wu = vw[u];
                        const float4 qa = qt4[u * 2];
                        const float4 qb = qt4[u * 2 + 1];
                        // 3 on the MUFU.TANH pipe, 5 on EX2+FMA pipe
                        a0 += wu * fast_tanh(qa.x + v);
                        a1 += wu * fast_tanh(qa.y + v);
                        a2 += wu * fast_tanh(qa.z + v);
                        a3 += wu * exp_tanh (qa.w + v);
                        a4 += wu * exp_tanh (qb.x + v);
                        a5 += wu * exp_tanh (qb.y + v);
                        a6 += wu * exp_tanh (qb.z + v);
                        a7 += wu * exp_tanh (qb.w + v);
                    }
#pragma unroll
                    for (int i = 0; i < 16; i++)
                        vb[i] = vn[i];
                }
#pragma unroll
                for (int i = 0; i < 16; i++) {       // epilogue: last 16 u
                    const int u = NU - 16 + i;
                    const float v  = vb[i];
                    const float wu = vw[u];
                    const float4 qa = qt4[u * 2];
                    const float4 qb = qt4[u * 2 + 1];
                    a0 += wu * fast_tanh(qa.x + v);
                    a1 += wu * fast_tanh(qa.y + v);
                    a2 += wu * fast_tanh(qa.z + v);
                    a3 += wu * exp_tanh (qa.w + v);
                    a4 += wu * exp_tanh (qb.x + v);
                    a5 += wu * exp_tanh (qb.y + v);
                    a6 += wu * exp_tanh (qb.z + v);
                    a7 += wu * exp_tanh (qb.w + v);
                }

                if (j < jcount) {
                    // causal mask -> exact 0 (excluded from softmax & context)
                    at4[j * 2]     = make_float4(j <= i0     ? a0 : 0.f,
                                                 j <= i0 + 1 ? a1 : 0.f,
                                                 j <= i0 + 2 ? a2 : 0.f,
                                                 j <= i0 + 3 ? a3 : 0.f);
                    at4[j * 2 + 1] = make_float4(j <= i0 + 4 ? a4 : 0.f,
                                                 j <= i0 + 5 ? a5 : 0.f,
                                                 j <= i0 + 6 ? a6 : 0.f,
                                                 j <= i0 + 7 ? a7 : 0.f);
                }
            }
        }
        __syncthreads();

        // ---- softmax: warp w owns query row i0+w, over j in [0, i0+w]
        {
            float* at = (float*)at4;
            const int cnt = i0 + w + 1;

            float m = -1e30f;
            for (int jj = lane; jj < cnt; jj += 32)
                m = fmaxf(m, at[jj * TI + w]);
#pragma unroll
            for (int o = 16; o; o >>= 1)
                m = fmaxf(m, __shfl_xor_sync(0xffffffffu, m, o));

            float ssum = 0.f;
            for (int jj = lane; jj < cnt; jj += 32) {
                const float e = __expf(at[jj * TI + w] - m);
                at[jj * TI + w] = e;
                ssum += e;
            }
#pragma unroll
            for (int o = 16; o; o >>= 1)
                ssum += __shfl_xor_sync(0xffffffffu, ssum, o);

            const float inv = 1.f / ssum;
            for (int jj = lane; jj < cnt; jj += 32)
                at[jj * TI + w] *= inv;
        }
        __syncthreads();

        // ---- Phase B: context, thread owns d column (D == 256 == blockDim)
        {
            const int d = tid;
            float c0 = 0.f, c1 = 0.f, c2 = 0.f, c3 = 0.f;
            float c4 = 0.f, c5 = 0.f, c6 = 0.f, c7 = 0.f;

            const float* vb2 = values + (size_t)(b * NS) * ND + d;

#pragma unroll 8
            for (int j = 0; j < jcount; j++) {
                const float  v  = vb2[(size_t)j * ND];  // coalesced 128B/warp
                const float4 p0 = at4[j * 2];           // LDS.128 broadcast
                const float4 p1 = at4[j * 2 + 1];
                c0 += p0.x * v;  c1 += p0.y * v;  c2 += p0.z * v;  c3 += p0.w * v;
                c4 += p1.x * v;  c5 += p1.y * v;  c6 += p1.z * v;  c7 += p1.w * v;
            }

            float cc[TI] = {c0, c1, c2, c3, c4, c5, c6, c7};
#pragma unroll
            for (int ti = 0; ti < TI; ti++)
                out[(size_t)(b * NS + i0 + ti) * ND + d] = cc[ti];
        }
        __syncthreads();   // smem safe for next half
    }
}

// ---------------------------------------------------------------------------
extern "C" void kernel_launch(void* const* d_in, const int* in_sizes, int n_in,
                              void* d_out, int out_size)
{
    const float* values = (const float*)d_in[0];
    const float* Wq     = (const float*)d_in[1];
    const float* Wv     = (const float*)d_in[2];
    const float* Vw     = (const float*)d_in[3];
    float* out = (float*)d_out;

    proj_kernel<<<(NB * NS) / 16, 256>>>(values, Wq, Wv);
    attn_kernel<<<dim3(NT / 2, NB), 256>>>(values, Vw, out);
}

// round 15
// speedup vs baseline: 1.3665x; 1.3665x over previous
#include <cuda_runtime.h>

#define NB 4
#define NS 512
#define ND 256
#define NU 128
#define TI 8
#define NT (NS / TI)   // 64 i-tiles per batch

// scratch (allocation-free rule: __device__ globals)
__device__ float g_Q [NB * NS * NU];        // [row][u]    1 MB
__device__ float g_Vt[NB * NU * NS];        // [b][u][j]   1 MB

__device__ __forceinline__ float fast_tanh(float x) {
    float r;
    asm("tanh.approx.f32 %0, %1;" : "=f"(r) : "f"(x));
    return r;
}

// ---------------------------------------------------------------------------
// Pass 1: Q = values @ Wq -> g_Q ;  V = values @ Wv -> g_Vt (transposed).
// 128 blocks x 256 thr. Block: 16 rows. Warp owns 2 rows; lane owns u-quad.
// W double-buffered in smem k-chunks of 32.
// ---------------------------------------------------------------------------
#define KC 32
__global__ __launch_bounds__(256) void proj_kernel(
    const float* __restrict__ values,
    const float* __restrict__ Wq,
    const float* __restrict__ Wv)
{
    __shared__ float4 sW[2][2][KC][NU / 4];  // [buf][mat][k][uq]  64 KB
    __shared__ float  vals[16][ND];          // 16 KB

    const int tid  = threadIdx.x;
    const int w    = tid >> 5;
    const int lane = tid & 31;
    const int r0   = blockIdx.x * 16;

    {
        const float4* g4 = (const float4*)(values + (size_t)r0 * ND);
        float4* s4 = (float4*)&vals[0][0];
#pragma unroll
        for (int i = 0; i < 4; i++)
            s4[tid + i * 256] = g4[tid + i * 256];
    }
    {
        const float4* wq4 = (const float4*)Wq;
        const float4* wv4 = (const float4*)Wv;
#pragma unroll
        for (int i = 0; i < 4; i++) {
            const int idx = tid + i * 256;
            sW[0][0][idx >> 5][idx & 31] = wq4[idx];
            sW[0][1][idx >> 5][idx & 31] = wv4[idx];
        }
    }
    __syncthreads();

    float4 aq0 = {0,0,0,0}, aq1 = {0,0,0,0};
    float4 av0 = {0,0,0,0}, av1 = {0,0,0,0};

    const float* vr0 = vals[2 * w + 0];
    const float* vr1 = vals[2 * w + 1];

#pragma unroll 1
    for (int c = 0; c < ND / KC; c++) {
        const int buf = c & 1;

        if (c + 1 < ND / KC) {
            const float4* wq4 = (const float4*)(Wq + (size_t)(c + 1) * KC * NU);
            const float4* wv4 = (const float4*)(Wv + (size_t)(c + 1) * KC * NU);
#pragma unroll
            for (int i = 0; i < 4; i++) {
                const int idx = tid + i * 256;
                sW[buf ^ 1][0][idx >> 5][idx & 31] = wq4[idx];
                sW[buf ^ 1][1][idx >> 5][idx & 31] = wv4[idx];
            }
        }

        const int kc = c * KC;
#pragma unroll 8
        for (int k = 0; k < KC; k++) {
            const float  x0 = vr0[kc + k];
            const float  x1 = vr1[kc + k];
            const float4 wq = sW[buf][0][k][lane];
            const float4 wv = sW[buf][1][k][lane];
            aq0.x += x0 * wq.x;  aq0.y += x0 * wq.y;  aq0.z += x0 * wq.z;  aq0.w += x0 * wq.w;
            aq1.x += x1 * wq.x;  aq1.y += x1 * wq.y;  aq1.z += x1 * wq.z;  aq1.w += x1 * wq.w;
            av0.x += x0 * wv.x;  av0.y += x0 * wv.y;  av0.z += x0 * wv.z;  av0.w += x0 * wv.w;
            av1.x += x1 * wv.x;  av1.y += x1 * wv.y;  av1.z += x1 * wv.z;  av1.w += x1 * wv.w;
        }
        __syncthreads();
    }

#pragma unroll
    for (int rr = 0; rr < 2; rr++) {
        const int row = r0 + 2 * w + rr;
        const float4 aq = rr ? aq1 : aq0;
        const float4 av = rr ? av1 : av0;
        ((float4*)(g_Q + (size_t)row * NU))[lane] = aq;

        const int b = row >> 9;
        const int s = row & (NS - 1);
        float* vt = g_Vt + ((size_t)b * NU + 4 * lane) * NS + s;
        vt[0 * NS] = av.x;
        vt[1 * NS] = av.y;
        vt[2 * NS] = av.z;
        vt[3 * NS] = av.w;
    }
}

// ---------------------------------------------------------------------------
// Pass 2 (fused): score(tanh) + causal softmax + context.
// Block processes tile pair (NT-1-x, x): j-work = 520 per block, uniform.
// grid (32, 4), 512 threads (16 warps = 4 per SMSP) -> feeds the MUFU pipe.
// Phase A: warp w sweeps j-chunks {w, w+16, ...}; 8-u register pipeline.
// softmax: warps 0-7, one row each.  Phase B: 2 row-halves x 256 d columns.
// ---------------------------------------------------------------------------
__global__ __launch_bounds__(512) void attn_kernel(
    const float* __restrict__ values,
    const float* __restrict__ Vw,
    float* __restrict__ out)
{
    __shared__ float4 at4[NS * 2];      // at[j][ti], 16 KB
    __shared__ float  qt[NU][TI];       // 4 KB
    __shared__ float  vw[NU];

    const int b   = blockIdx.y;
    const int tid = threadIdx.x;
    const int w    = tid >> 5;
    const int lane = tid & 31;

    if (tid < NU) vw[tid] = Vw[tid];

#pragma unroll 1
    for (int half = 0; half < 2; half++) {
        // big tile first, then its small partner
        const int it = half == 0 ? (NT - 1 - blockIdx.x) : blockIdx.x;
        const int i0 = it * TI;
        const int jcount = i0 + TI;

        // stage q transposed: 1024 elems, 2 per thread
        {
            const int u = tid & 127, t2 = tid >> 7;  // t2 in 0..3
            qt[u][t2 + 0] = g_Q[(b * NS + i0 + t2 + 0) * NU + u];
            qt[u][t2 + 4] = g_Q[(b * NS + i0 + t2 + 4) * NU + u];
        }
        __syncthreads();

        // ---- Phase A: scores, warp-chunks of 32 j, 8-u pipelined loads
        {
            const int nJ32 = (jcount + 31) >> 5;
            const float4* qt4 = (const float4*)&qt[0][0];

            for (int jt = w; jt < nJ32; jt += 16) {
                const int j = jt * 32 + lane;        // always < NS
                const float* vp = g_Vt + (size_t)b * (NU * NS) + j;

                float a0 = 0.f, a1 = 0.f, a2 = 0.f, a3 = 0.f;
                float a4 = 0.f, a5 = 0.f, a6 = 0.f, a7 = 0.f;

                float vb[8];
#pragma unroll
                for (int i = 0; i < 8; i++)          // prime: 8 LDGs in flight
                    vb[i] = vp[i * NS];

#pragma unroll 1
                for (int ub = 0; ub < NU - 8; ub += 8) {
                    float vn[8];
#pragma unroll
                    for (int i = 0; i < 8; i++)      // prefetch next 8 (MLP 8)
                        vn[i] = vp[(ub + 8 + i) * NS];
#pragma unroll
                    for (int i = 0; i < 8; i++) {
                        const int u = ub + i;
                        const float v  = vb[i];
                        const float wu = vw[u];
                        const float4 qa = qt4[u * 2];
                        const float4 qb = qt4[u * 2 + 1];
                        a0 += wu * fast_tanh(qa.x + v);
                        a1 += wu * fast_tanh(qa.y + v);
                        a2 += wu * fast_tanh(qa.z + v);
                        a3 += wu * fast_tanh(qa.w + v);
                        a4 += wu * fast_tanh(qb.x + v);
                        a5 += wu * fast_tanh(qb.y + v);
                        a6 += wu * fast_tanh(qb.z + v);
                        a7 += wu * fast_tanh(qb.w + v);
                    }
#pragma unroll
                    for (int i = 0; i < 8; i++)
                        vb[i] = vn[i];
                }
#pragma unroll
                for (int i = 0; i < 8; i++) {        // epilogue: last 8 u
                    const int u = NU - 8 + i;
                    const float v  = vb[i];
                    const float wu = vw[u];
                    const float4 qa = qt4[u * 2];
                    const float4 qb = qt4[u * 2 + 1];
                    a0 += wu * fast_tanh(qa.x + v);
                    a1 += wu * fast_tanh(qa.y + v);
                    a2 += wu * fast_tanh(qa.z + v);
                    a3 += wu * fast_tanh(qa.w + v);
                    a4 += wu * fast_tanh(qb.x + v);
                    a5 += wu * fast_tanh(qb.y + v);
                    a6 += wu * fast_tanh(qb.z + v);
                    a7 += wu * fast_tanh(qb.w + v);
                }

                if (j < jcount) {
                    // causal mask -> exact 0 (excluded from softmax & context)
                    at4[j * 2]     = make_float4(j <= i0     ? a0 : 0.f,
                                                 j <= i0 + 1 ? a1 : 0.f,
                                                 j <= i0 + 2 ? a2 : 0.f,
                                                 j <= i0 + 3 ? a3 : 0.f);
                    at4[j * 2 + 1] = make_float4(j <= i0 + 4 ? a4 : 0.f,
                                                 j <= i0 + 5 ? a5 : 0.f,
                                                 j <= i0 + 6 ? a6 : 0.f,
                                                 j <= i0 + 7 ? a7 : 0.f);
                }
            }
        }
        __syncthreads();

        // ---- softmax: warps 0-7, warp w owns query row i0+w over [0, i0+w]
        if (w < TI) {
            float* at = (float*)at4;
            const int cnt = i0 + w + 1;

            float m = -1e30f;
            for (int jj = lane; jj < cnt; jj += 32)
                m = fmaxf(m, at[jj * TI + w]);
#pragma unroll
            for (int o = 16; o; o >>= 1)
                m = fmaxf(m, __shfl_xor_sync(0xffffffffu, m, o));

            float ssum = 0.f;
            for (int jj = lane; jj < cnt; jj += 32) {
                const float e = __expf(at[jj * TI + w] - m);
                at[jj * TI + w] = e;
                ssum += e;
            }
#pragma unroll
            for (int o = 16; o; o >>= 1)
                ssum += __shfl_xor_sync(0xffffffffu, ssum, o);

            const float inv = 1.f / ssum;
            for (int jj = lane; jj < cnt; jj += 32)
                at[jj * TI + w] *= inv;
        }
        __syncthreads();

        // ---- Phase B: context. 512 thr = 2 row-halves x 256 d columns.
        {
            const int d  = tid & 255;
            const int hh = tid >> 8;                 // 0: rows 0-3, 1: rows 4-7
            float c0 = 0.f, c1 = 0.f, c2 = 0.f, c3 = 0.f;

            const float* vb2 = values + (size_t)(b * NS) * ND + d;

#pragma unroll 8
            for (int j = 0; j < jcount; j++) {
                const float  v = vb2[(size_t)j * ND];    // coalesced 128B/warp
                const float4 p = at4[j * 2 + hh];        // LDS.128 broadcast
                c0 += p.x * v;  c1 += p.y * v;  c2 += p.z * v;  c3 += p.w * v;
            }

            float cc[4] = {c0, c1, c2, c3};
#pragma unroll
            for (int r = 0; r < 4; r++)
                out[(size_t)(b * NS + i0 + hh * 4 + r) * ND + d] = cc[r];
        }
        __syncthreads();   // smem safe for next half
    }
}

// ---------------------------------------------------------------------------
extern "C" void kernel_launch(void* const* d_in, const int* in_sizes, int n_in,
                              void* d_out, int out_size)
{
    const float* values = (const float*)d_in[0];
    const float* Wq     = (const float*)d_in[1];
    const float* Wv     = (const float*)d_in[2];
    const float* Vw     = (const float*)d_in[3];
    float* out = (float*)d_out;

    proj_kernel<<<(NB * NS) / 16, 256>>>(values, Wq, Wv);
    attn_kernel<<<dim3(NT / 2, NB), 512>>>(values, Vw, out);
}